// round 1
// baseline (speedup 1.0000x reference)
#include <cuda_runtime.h>
#include <cstdint>

// Problem dims (fixed for this problem instance)
#define T_SEQ 2048
#define E_DIM 1024
#define N_HEADS 16
#define D_HEAD 64
#define NB 10
#define ML 2048
#define R_DIM (NB * N_HEADS)  // 160

// ---------------------------------------------------------------------------
// Scratch (device globals; no runtime allocation allowed)
// ---------------------------------------------------------------------------
__device__ float g_Q[T_SEQ * E_DIM];
__device__ float g_K[T_SEQ * E_DIM];
__device__ float g_V[T_SEQ * E_DIM];
__device__ float g_R[T_SEQ * R_DIM];
__device__ float g_AO[T_SEQ * E_DIM];

// ---------------------------------------------------------------------------
// SGEMM: C[M,N] = A[M,K] @ B[K,N] (+ bias[N])
// Row-major everywhere. BM=BN=128, BK=16, 256 threads, 8x8 per-thread tiles.
// ---------------------------------------------------------------------------
template <int HAS_BIAS>
__global__ __launch_bounds__(256) void sgemm_kernel(
    const float* __restrict__ A, const float* __restrict__ B,
    const float* __restrict__ bias, float* __restrict__ C,
    int M, int N, int K)
{
    __shared__ float As[16][132];  // transposed: As[k][m], padded
    __shared__ float Bs[16][128];  // Bs[k][n]

    const int tid = threadIdx.x;
    const int tx = tid & 15;        // 0..15 -> 8 columns each
    const int ty = tid >> 4;        // 0..15 -> 8 rows each
    const int m0 = blockIdx.y * 128;
    const int n0 = blockIdx.x * 128;

    float acc[8][8];
#pragma unroll
    for (int i = 0; i < 8; i++)
#pragma unroll
        for (int j = 0; j < 8; j++) acc[i][j] = 0.f;

    for (int k0 = 0; k0 < K; k0 += 16) {
        // ---- load A tile (128 x 16) transposed into As[k][m] ----
#pragma unroll
        for (int it = 0; it < 2; it++) {
            int v = tid + it * 256;          // 0..511 float4s
            int row = v >> 2;                // 0..127
            int col = (v & 3) * 4;           // 0,4,8,12
            float4 a4 = make_float4(0.f, 0.f, 0.f, 0.f);
            if (m0 + row < M) {
                a4 = *reinterpret_cast<const float4*>(&A[(size_t)(m0 + row) * K + k0 + col]);
            }
            As[col + 0][row] = a4.x;
            As[col + 1][row] = a4.y;
            As[col + 2][row] = a4.z;
            As[col + 3][row] = a4.w;
        }
        // ---- load B tile (16 x 128) into Bs[k][n] ----
#pragma unroll
        for (int it = 0; it < 2; it++) {
            int v = tid + it * 256;
            int row = v >> 5;                // 0..15
            int col = (v & 31) * 4;          // 0..124
            float4 b4 = make_float4(0.f, 0.f, 0.f, 0.f);
            if (n0 + col < N) {
                b4 = *reinterpret_cast<const float4*>(&B[(size_t)(k0 + row) * N + n0 + col]);
            }
            *reinterpret_cast<float4*>(&Bs[row][col]) = b4;
        }
        __syncthreads();

#pragma unroll
        for (int kk = 0; kk < 16; kk++) {
            float a[8], b[8];
            float4 af0 = *reinterpret_cast<float4*>(&As[kk][ty * 8]);
            float4 af1 = *reinterpret_cast<float4*>(&As[kk][ty * 8 + 4]);
            float4 bf0 = *reinterpret_cast<float4*>(&Bs[kk][tx * 8]);
            float4 bf1 = *reinterpret_cast<float4*>(&Bs[kk][tx * 8 + 4]);
            a[0] = af0.x; a[1] = af0.y; a[2] = af0.z; a[3] = af0.w;
            a[4] = af1.x; a[5] = af1.y; a[6] = af1.z; a[7] = af1.w;
            b[0] = bf0.x; b[1] = bf0.y; b[2] = bf0.z; b[3] = bf0.w;
            b[4] = bf1.x; b[5] = bf1.y; b[6] = bf1.z; b[7] = bf1.w;
#pragma unroll
            for (int i = 0; i < 8; i++)
#pragma unroll
                for (int j = 0; j < 8; j++)
                    acc[i][j] = fmaf(a[i], b[j], acc[i][j]);
        }
        __syncthreads();
    }

    // ---- epilogue ----
#pragma unroll
    for (int i = 0; i < 8; i++) {
        int row = m0 + ty * 8 + i;
        if (row >= M) continue;
#pragma unroll
        for (int j = 0; j < 8; j++) {
            int col = n0 + tx * 8 + j;
            if (col >= N) continue;
            float v = acc[i][j];
            if (HAS_BIAS) v += bias[col];
            C[(size_t)row * N + col] = v;
        }
    }
}

// ---------------------------------------------------------------------------
// Flash-attention with relative banded bias.
// Block: (q-tile of 64) x head. 256 threads; 4x4 S/O microtile per thread.
// S[q,k] = (Q.K)/8 + sum_n R[q,n]*b_nd[n, q-k]   (causal, rel in [0, ML))
// ---------------------------------------------------------------------------
struct AttnSmem {
    float Qs[64][68];   // [d][q]  (transposed, pre-scaled by 1/8)
    float Ks[64][68];   // [d][k]  (transposed)
    float Vs[64][68];   // [k][d]
    float Ps[64][68];   // [k][q]  (transposed probs)
    float Bsl[NB][132]; // b_nd slab: Bsl[n][j] = b_nd[n][q0-k0-63+j]
    float Rsm[64][12];  // R fragment for this q tile / head
};

__global__ __launch_bounds__(256) void attn_kernel(
    const float* __restrict__ Q, const float* __restrict__ K,
    const float* __restrict__ V, const float* __restrict__ R,
    const float* __restrict__ b_nd, float* __restrict__ AO)
{
    extern __shared__ char smem_raw[];
    AttnSmem& S = *reinterpret_cast<AttnSmem*>(smem_raw);

    const int h = blockIdx.y;
    const int qb = blockIdx.x;
    const int q0 = qb * 64;
    const int tid = threadIdx.x;
    const int tx = tid & 15;   // 4 k / v columns
    const int ty = tid >> 4;   // 4 q rows

    // ---- load Q tile (transposed + pre-scaled) and R fragment ----
#pragma unroll
    for (int it = 0; it < 4; it++) {
        int v = tid + it * 256;          // 1024 float4s
        int row = v >> 4;                // 0..63
        int c4 = (v & 15) * 4;           // 0..60
        float4 q4 = *reinterpret_cast<const float4*>(
            &Q[(size_t)(q0 + row) * E_DIM + h * D_HEAD + c4]);
        S.Qs[c4 + 0][row] = q4.x * 0.125f;
        S.Qs[c4 + 1][row] = q4.y * 0.125f;
        S.Qs[c4 + 2][row] = q4.z * 0.125f;
        S.Qs[c4 + 3][row] = q4.w * 0.125f;
    }
    for (int idx = tid; idx < 64 * NB; idx += 256) {
        int row = idx / NB, n = idx % NB;
        S.Rsm[row][n] = R[(size_t)(q0 + row) * R_DIM + h * NB + n];
    }
    __syncthreads();

    float r_frag[4][NB];
#pragma unroll
    for (int i = 0; i < 4; i++)
#pragma unroll
        for (int n = 0; n < NB; n++) r_frag[i][n] = S.Rsm[4 * ty + i][n];

    float m_run[4], l_run[4], o_acc[4][4];
#pragma unroll
    for (int i = 0; i < 4; i++) {
        m_run[i] = -1e30f;
        l_run[i] = 0.f;
#pragma unroll
        for (int j = 0; j < 4; j++) o_acc[i][j] = 0.f;
    }

    for (int kt = 0; kt <= qb; kt++) {
        const int k0 = kt * 64;
        __syncthreads();  // previous AV reads done before overwriting tiles

        // ---- load K (transposed) and V (row-major) tiles ----
#pragma unroll
        for (int it = 0; it < 4; it++) {
            int v = tid + it * 256;
            int row = v >> 4;
            int c4 = (v & 15) * 4;
            float4 k4 = *reinterpret_cast<const float4*>(
                &K[(size_t)(k0 + row) * E_DIM + h * D_HEAD + c4]);
            S.Ks[c4 + 0][row] = k4.x;
            S.Ks[c4 + 1][row] = k4.y;
            S.Ks[c4 + 2][row] = k4.z;
            S.Ks[c4 + 3][row] = k4.w;
            float4 v4 = *reinterpret_cast<const float4*>(
                &V[(size_t)(k0 + row) * E_DIM + h * D_HEAD + c4]);
            *reinterpret_cast<float4*>(&S.Vs[row][c4]) = v4;
        }
        // ---- load b_nd slab: rel = (q0-k0) + (qi-ki), qi-ki in [-63,63] ----
        const int relb = q0 - k0 - 63;
        for (int idx = tid; idx < NB * 128; idx += 256) {
            int n = idx >> 7, j = idx & 127;
            int c = relb + j;
            S.Bsl[n][j] = (c >= 0 && c < ML) ? b_nd[n * ML + c] : 0.f;
        }
        __syncthreads();

        // ---- S = Qs^T Ks (Q pre-scaled) ----
        float s[4][4];
#pragma unroll
        for (int i = 0; i < 4; i++)
#pragma unroll
            for (int j = 0; j < 4; j++) s[i][j] = 0.f;

#pragma unroll
        for (int d = 0; d < 64; d++) {
            float a[4], b[4];
            float4 af = *reinterpret_cast<float4*>(&S.Qs[d][4 * ty]);
            float4 bf = *reinterpret_cast<float4*>(&S.Ks[d][4 * tx]);
            a[0] = af.x; a[1] = af.y; a[2] = af.z; a[3] = af.w;
            b[0] = bf.x; b[1] = bf.y; b[2] = bf.z; b[3] = bf.w;
#pragma unroll
            for (int i = 0; i < 4; i++)
#pragma unroll
                for (int j = 0; j < 4; j++)
                    s[i][j] = fmaf(a[i], b[j], s[i][j]);
        }

        // ---- add relative bias; apply causal mask on diagonal tile ----
        const bool diag = (kt == qb);
#pragma unroll
        for (int i = 0; i < 4; i++) {
            const int qi = 4 * ty + i;
#pragma unroll
            for (int j = 0; j < 4; j++) {
                const int ki = 4 * tx + j;
                const int bidx = qi - ki + 63;
                float e = 0.f;
#pragma unroll
                for (int n = 0; n < NB; n++)
                    e = fmaf(r_frag[i][n], S.Bsl[n][bidx], e);
                s[i][j] += e;
                if (diag && ki > qi) s[i][j] = -1e30f;
            }
        }

        // ---- online softmax (16-lane row groups) ----
#pragma unroll
        for (int i = 0; i < 4; i++) {
            float mt = fmaxf(fmaxf(s[i][0], s[i][1]), fmaxf(s[i][2], s[i][3]));
#pragma unroll
            for (int o = 8; o > 0; o >>= 1)
                mt = fmaxf(mt, __shfl_xor_sync(0xffffffffu, mt, o));
            float mn = fmaxf(m_run[i], mt);
            float corr = __expf(m_run[i] - mn);
            float ps = 0.f;
#pragma unroll
            for (int j = 0; j < 4; j++) {
                float p = __expf(s[i][j] - mn);
                ps += p;
                S.Ps[4 * tx + j][4 * ty + i] = p;
            }
#pragma unroll
            for (int o = 8; o > 0; o >>= 1)
                ps += __shfl_xor_sync(0xffffffffu, ps, o);
            l_run[i] = l_run[i] * corr + ps;
            m_run[i] = mn;
#pragma unroll
            for (int j = 0; j < 4; j++) o_acc[i][j] *= corr;
        }
        __syncthreads();

        // ---- O += P @ V ----
#pragma unroll
        for (int k = 0; k < 64; k++) {
            float a[4], b[4];
            float4 af = *reinterpret_cast<float4*>(&S.Ps[k][4 * ty]);
            float4 bf = *reinterpret_cast<float4*>(&S.Vs[k][4 * tx]);
            a[0] = af.x; a[1] = af.y; a[2] = af.z; a[3] = af.w;
            b[0] = bf.x; b[1] = bf.y; b[2] = bf.z; b[3] = bf.w;
#pragma unroll
            for (int i = 0; i < 4; i++)
#pragma unroll
                for (int j = 0; j < 4; j++)
                    o_acc[i][j] = fmaf(a[i], b[j], o_acc[i][j]);
        }
    }

    // ---- epilogue: normalize and write merged-head layout ----
#pragma unroll
    for (int i = 0; i < 4; i++) {
        float inv = 1.f / l_run[i];
        int row = q0 + 4 * ty + i;
#pragma unroll
        for (int j = 0; j < 4; j++)
            AO[(size_t)row * E_DIM + h * D_HEAD + 4 * tx + j] = o_acc[i][j] * inv;
    }
}

// ---------------------------------------------------------------------------
// Host launcher
// ---------------------------------------------------------------------------
extern "C" void kernel_launch(void* const* d_in, const int* in_sizes, int n_in,
                              void* d_out, int out_size)
{
    const float* X      = (const float*)d_in[0];
    const float* W_q    = (const float*)d_in[1];
    const float* b_q    = (const float*)d_in[2];
    const float* W_k    = (const float*)d_in[3];
    const float* W_v    = (const float*)d_in[4];
    const float* W_proj = (const float*)d_in[5];
    const float* b_proj = (const float*)d_in[6];
    const float* W_r    = (const float*)d_in[7];
    const float* b_r    = (const float*)d_in[8];
    const float* b_nd   = (const float*)d_in[9];

    float *Qp, *Kp, *Vp, *Rp, *AOp;
    cudaGetSymbolAddress((void**)&Qp, g_Q);
    cudaGetSymbolAddress((void**)&Kp, g_K);
    cudaGetSymbolAddress((void**)&Vp, g_V);
    cudaGetSymbolAddress((void**)&Rp, g_R);
    cudaGetSymbolAddress((void**)&AOp, g_AO);

    dim3 blk(256);

    // Projections
    sgemm_kernel<1><<<dim3(8, 16), blk>>>(X, W_q, b_q, Qp, T_SEQ, E_DIM, E_DIM);
    sgemm_kernel<0><<<dim3(8, 16), blk>>>(X, W_k, nullptr, Kp, T_SEQ, E_DIM, E_DIM);
    sgemm_kernel<0><<<dim3(8, 16), blk>>>(X, W_v, nullptr, Vp, T_SEQ, E_DIM, E_DIM);
    sgemm_kernel<1><<<dim3(2, 16), blk>>>(X, W_r, b_r, Rp, T_SEQ, R_DIM, E_DIM);

    // Attention (causal flash + relative bias)
    int smem = (int)sizeof(AttnSmem);
    cudaFuncSetAttribute(attn_kernel, cudaFuncAttributeMaxDynamicSharedMemorySize, smem);
    attn_kernel<<<dim3(T_SEQ / 64, N_HEADS), blk, smem>>>(Qp, Kp, Vp, Rp, b_nd, AOp);

    // Output projection -> d_out
    sgemm_kernel<1><<<dim3(8, 16), blk>>>(AOp, W_proj, b_proj, (float*)d_out,
                                          T_SEQ, E_DIM, E_DIM);
}

// round 3
// speedup vs baseline: 1.6802x; 1.6802x over previous
#include <cuda_runtime.h>
#include <cuda_bf16.h>
#include <cstdint>

// Problem dims (fixed)
#define T_SEQ 2048
#define E_DIM 1024
#define N_HEADS 16
#define D_HEAD 64
#define NB 10
#define ML 2048
#define NQKVR 3232          // 1024*3 + 160
#define WT_ROWS 4256        // 3232 (QKVR) + 1024 (proj)

// ---------------------------------------------------------------------------
// Scratch (device globals; no runtime allocation allowed)
// ---------------------------------------------------------------------------
__device__ __nv_bfloat16 g_Xh[T_SEQ * E_DIM];
__device__ __nv_bfloat16 g_Xl[T_SEQ * E_DIM];
__device__ __nv_bfloat16 g_WTh[WT_ROWS * E_DIM];
__device__ __nv_bfloat16 g_WTl[WT_ROWS * E_DIM];
__device__ __nv_bfloat16 g_AOh[T_SEQ * E_DIM];
__device__ __nv_bfloat16 g_AOl[T_SEQ * E_DIM];
__device__ float g_QKVR[T_SEQ * NQKVR];
__device__ float g_AO[T_SEQ * E_DIM];
__device__ float g_bias[NQKVR];

// ---------------------------------------------------------------------------
// PTX helpers (sm_80-baseline ISA only: mma.sync / ldmatrix / cp.async)
// ---------------------------------------------------------------------------
__device__ __forceinline__ uint32_t smem_u32(const void* p) {
    uint32_t a;
    asm("{ .reg .u64 t; cvta.to.shared.u64 t, %1; cvt.u32.u64 %0, t; }"
        : "=r"(a) : "l"(p));
    return a;
}

#define LDSM_X4(r, a)                                                         \
    asm volatile("ldmatrix.sync.aligned.m8n8.x4.shared.b16 {%0,%1,%2,%3}, [%4];" \
                 : "=r"((r)[0]), "=r"((r)[1]), "=r"((r)[2]), "=r"((r)[3])     \
                 : "r"(a))
#define LDSM_X2(r, a)                                                         \
    asm volatile("ldmatrix.sync.aligned.m8n8.x2.shared.b16 {%0,%1}, [%2];"    \
                 : "=r"((r)[0]), "=r"((r)[1]) : "r"(a))
#define MMA16816(d, a, b)                                                     \
    asm volatile("mma.sync.aligned.m16n8k16.row.col.f32.bf16.bf16.f32 "       \
                 "{%0,%1,%2,%3},{%4,%5,%6,%7},{%8,%9},{%0,%1,%2,%3};"         \
                 : "+f"((d)[0]), "+f"((d)[1]), "+f"((d)[2]), "+f"((d)[3])     \
                 : "r"((a)[0]), "r"((a)[1]), "r"((a)[2]), "r"((a)[3]),        \
                   "r"((b)[0]), "r"((b)[1]))
#define CP_ASYNC16(dst, src)                                                  \
    asm volatile("cp.async.cg.shared.global [%0], [%1], 16;"                  \
                 :: "r"(dst), "l"(src))
#define CP_COMMIT asm volatile("cp.async.commit_group;" ::: "memory")
#define CP_WAIT(n) asm volatile("cp.async.wait_group %0;" :: "n"(n) : "memory")

// ---------------------------------------------------------------------------
// Elementwise fp32 -> bf16 hi/lo split
// ---------------------------------------------------------------------------
__global__ void fsplit_kernel(const float* __restrict__ s,
                              __nv_bfloat16* __restrict__ dh,
                              __nv_bfloat16* __restrict__ dl, int n) {
    int i = blockIdx.x * blockDim.x + threadIdx.x;
    if (i < n) {
        float x = s[i];
        __nv_bfloat16 h = __float2bfloat16(x);
        dh[i] = h;
        dl[i] = __float2bfloat16(x - __bfloat162float(h));
    }
}

// Transpose W [1024][N] -> WT [N][1024] (bf16 hi/lo), rows written at rowoff.
__global__ void tsplit_kernel(const float* __restrict__ W, int N,
                              __nv_bfloat16* __restrict__ dh,
                              __nv_bfloat16* __restrict__ dl, int rowoff) {
    __shared__ float t[32][33];
    const int n0 = blockIdx.x * 32, k0 = blockIdx.y * 32;
    const int tx = threadIdx.x, ty = threadIdx.y;  // 32 x 8
#pragma unroll
    for (int r = 0; r < 4; r++)
        t[ty + 8 * r][tx] = W[(size_t)(k0 + ty + 8 * r) * N + n0 + tx];
    __syncthreads();
#pragma unroll
    for (int r = 0; r < 4; r++) {
        float x = t[tx][ty + 8 * r];
        __nv_bfloat16 h = __float2bfloat16(x);
        size_t o = (size_t)(rowoff + n0 + ty + 8 * r) * E_DIM + k0 + tx;
        dh[o] = h;
        dl[o] = __float2bfloat16(x - __bfloat162float(h));
    }
}

__global__ void biaspack_kernel(const float* __restrict__ bq,
                                const float* __restrict__ br,
                                float* __restrict__ o) {
    int i = blockIdx.x * 256 + threadIdx.x;
    if (i < NQKVR)
        o[i] = i < 1024 ? bq[i] : (i >= 3072 ? br[i - 3072] : 0.f);
}

// ---------------------------------------------------------------------------
// mma.sync GEMM: C[2048, N] = A[2048,1024] @ BT[N,1024]^T (+ bias)
// 3-term bf16 split: D = Ah*Bh + Ah*Bl + Al*Bh (fp32 accum in HMMA)
// CTA tile 128x128, BK=64, 8 warps (2m x 4n), warp tile 64x32.
// Double-buffered cp.async. SMEM swizzle: chunk ^= row&7 (16B chunks/128B row)
// ---------------------------------------------------------------------------
#define GEMM_SMEM (2 * 4 * 16384)   // 131072

__global__ __launch_bounds__(256, 1) void gemm_mma3(
    const __nv_bfloat16* __restrict__ Ah, const __nv_bfloat16* __restrict__ Al,
    const __nv_bfloat16* __restrict__ Bh, const __nv_bfloat16* __restrict__ Bl,
    const float* __restrict__ bias, float* __restrict__ C, int N, int ldc)
{
    extern __shared__ char smraw[];
    const uint32_t sb = smem_u32(smraw);
    const int tid = threadIdx.x, wid = tid >> 5, lane = tid & 31;
    const int m0 = blockIdx.y * 128, n0 = blockIdx.x * 128;
    const int ntile = min(128, N - n0);

    const int wm = (wid & 1) * 64;       // warp m offset in tile
    const int wn = (wid >> 1) * 32;      // warp n offset in tile

    const __nv_bfloat16* srcs[4];
    srcs[0] = Ah + (size_t)m0 * E_DIM;
    srcs[1] = Al + (size_t)m0 * E_DIM;
    srcs[2] = Bh + (size_t)n0 * E_DIM;
    srcs[3] = Bl + (size_t)n0 * E_DIM;

    // ---- async tile loader: 4 arrays x 128 rows x 64 k (128B/row) ----
    auto load_tile = [&](int kt, int buf) {
        const uint32_t base = sb + buf * 65536;
#pragma unroll
        for (int arr = 0; arr < 4; arr++) {
            const __nv_bfloat16* s = srcs[arr] + kt * 64;
#pragma unroll
            for (int i = 0; i < 4; i++) {
                int idx = tid + i * 256;
                int row = idx >> 3, c = idx & 7;
                const void* src = s + (size_t)row * E_DIM + c * 8;
                uint32_t dst = base + arr * 16384 +
                               (uint32_t)(row * 128 + ((c ^ (row & 7)) << 4));
                CP_ASYNC16(dst, src);
            }
        }
    };

    float acc[4][4][4];
#pragma unroll
    for (int mt = 0; mt < 4; mt++)
#pragma unroll
        for (int nt = 0; nt < 4; nt++)
#pragma unroll
            for (int r = 0; r < 4; r++) acc[mt][nt][r] = 0.f;

    const int lr = lane & 7;       // row within 8x8 matrix
    const int ls = lane >> 3;      // ldmatrix address group 0..3

    load_tile(0, 0);
    CP_COMMIT;

    for (int kt = 0; kt < 16; kt++) {
        if (kt + 1 < 16) {
            load_tile(kt + 1, (kt + 1) & 1);
            CP_COMMIT;
            CP_WAIT(1);
        } else {
            CP_WAIT(0);
        }
        __syncthreads();

        const uint32_t cb = sb + (kt & 1) * 65536;
#pragma unroll
        for (int ks = 0; ks < 4; ks++) {
            uint32_t afh[4][4], afl[4][4], bfh[4][2], bfl[4][2];
#pragma unroll
            for (int mt = 0; mt < 4; mt++) {
                int row = wm + mt * 16 + ((ls & 1) << 3) + lr;
                int ch = (ks << 1) + (ls >> 1);
                uint32_t off = (uint32_t)(row * 128 + ((ch ^ (row & 7)) << 4));
                LDSM_X4(afh[mt], cb + off);
                LDSM_X4(afl[mt], cb + 16384 + off);
            }
#pragma unroll
            for (int nt = 0; nt < 4; nt++) {
                int row = wn + nt * 8 + lr;
                int ch = (ks << 1) + (ls & 1);
                uint32_t off = (uint32_t)(row * 128 + ((ch ^ (row & 7)) << 4));
                LDSM_X2(bfh[nt], cb + 32768 + off);
                LDSM_X2(bfl[nt], cb + 49152 + off);
            }
#pragma unroll
            for (int mt = 0; mt < 4; mt++)
#pragma unroll
                for (int nt = 0; nt < 4; nt++) {
                    MMA16816(acc[mt][nt], afh[mt], bfh[nt]);
                    MMA16816(acc[mt][nt], afh[mt], bfl[nt]);
                    MMA16816(acc[mt][nt], afl[mt], bfh[nt]);
                }
        }
        __syncthreads();
    }

    // ---- epilogue ----
#pragma unroll
    for (int mt = 0; mt < 4; mt++) {
        const int r0 = m0 + wm + mt * 16 + (lane >> 2);
#pragma unroll
        for (int nt = 0; nt < 4; nt++) {
            const int cloc = wn + nt * 8 + ((lane & 3) << 1);
            if (cloc < ntile) {
                const int col = n0 + cloc;
                const float bx = bias[col], by = bias[col + 1];
                float2 v0 = make_float2(acc[mt][nt][0] + bx, acc[mt][nt][1] + by);
                float2 v1 = make_float2(acc[mt][nt][2] + bx, acc[mt][nt][3] + by);
                *reinterpret_cast<float2*>(C + (size_t)r0 * ldc + col) = v0;
                *reinterpret_cast<float2*>(C + (size_t)(r0 + 8) * ldc + col) = v1;
            }
        }
    }
}

// ---------------------------------------------------------------------------
// Flash-attention with relative banded bias (fp32; reads fused QKVR buffer).
// ---------------------------------------------------------------------------
struct AttnSmem {
    float Qs[64][68];
    float Ks[64][68];
    float Vs[64][68];
    float Ps[64][68];
    float Bsl[NB][132];
    float Rsm[64][12];
};

__global__ __launch_bounds__(256) void attn_kernel(
    const float* __restrict__ QKVR, const float* __restrict__ b_nd,
    float* __restrict__ AO)
{
    extern __shared__ char smem_raw[];
    AttnSmem& S = *reinterpret_cast<AttnSmem*>(smem_raw);

    const int h = blockIdx.y;
    const int qb = blockIdx.x;
    const int q0 = qb * 64;
    const int tid = threadIdx.x;
    const int tx = tid & 15;
    const int ty = tid >> 4;

    const int qoff = h * D_HEAD;
    const int koff = 1024 + h * D_HEAD;
    const int voff = 2048 + h * D_HEAD;
    const int roff = 3072 + h * NB;

#pragma unroll
    for (int it = 0; it < 4; it++) {
        int v = tid + it * 256;
        int row = v >> 4;
        int c4 = (v & 15) * 4;
        float4 q4 = *reinterpret_cast<const float4*>(
            &QKVR[(size_t)(q0 + row) * NQKVR + qoff + c4]);
        S.Qs[c4 + 0][row] = q4.x * 0.125f;
        S.Qs[c4 + 1][row] = q4.y * 0.125f;
        S.Qs[c4 + 2][row] = q4.z * 0.125f;
        S.Qs[c4 + 3][row] = q4.w * 0.125f;
    }
    for (int idx = tid; idx < 64 * NB; idx += 256) {
        int row = idx / NB, n = idx % NB;
        S.Rsm[row][n] = QKVR[(size_t)(q0 + row) * NQKVR + roff + n];
    }
    __syncthreads();

    float r_frag[4][NB];
#pragma unroll
    for (int i = 0; i < 4; i++)
#pragma unroll
        for (int n = 0; n < NB; n++) r_frag[i][n] = S.Rsm[4 * ty + i][n];

    float m_run[4], l_run[4], o_acc[4][4];
#pragma unroll
    for (int i = 0; i < 4; i++) {
        m_run[i] = -1e30f;
        l_run[i] = 0.f;
#pragma unroll
        for (int j = 0; j < 4; j++) o_acc[i][j] = 0.f;
    }

    for (int kt = 0; kt <= qb; kt++) {
        const int k0 = kt * 64;
        __syncthreads();

#pragma unroll
        for (int it = 0; it < 4; it++) {
            int v = tid + it * 256;
            int row = v >> 4;
            int c4 = (v & 15) * 4;
            float4 k4 = *reinterpret_cast<const float4*>(
                &QKVR[(size_t)(k0 + row) * NQKVR + koff + c4]);
            S.Ks[c4 + 0][row] = k4.x;
            S.Ks[c4 + 1][row] = k4.y;
            S.Ks[c4 + 2][row] = k4.z;
            S.Ks[c4 + 3][row] = k4.w;
            float4 v4 = *reinterpret_cast<const float4*>(
                &QKVR[(size_t)(k0 + row) * NQKVR + voff + c4]);
            *reinterpret_cast<float4*>(&S.Vs[row][c4]) = v4;
        }
        const int relb = q0 - k0 - 63;
        for (int idx = tid; idx < NB * 128; idx += 256) {
            int n = idx >> 7, j = idx & 127;
            int c = relb + j;
            S.Bsl[n][j] = (c >= 0 && c < ML) ? b_nd[n * ML + c] : 0.f;
        }
        __syncthreads();

        float s[4][4];
#pragma unroll
        for (int i = 0; i < 4; i++)
#pragma unroll
            for (int j = 0; j < 4; j++) s[i][j] = 0.f;

#pragma unroll
        for (int d = 0; d < 64; d++) {
            float a[4], b[4];
            float4 af = *reinterpret_cast<float4*>(&S.Qs[d][4 * ty]);
            float4 bf = *reinterpret_cast<float4*>(&S.Ks[d][4 * tx]);
            a[0] = af.x; a[1] = af.y; a[2] = af.z; a[3] = af.w;
            b[0] = bf.x; b[1] = bf.y; b[2] = bf.z; b[3] = bf.w;
#pragma unroll
            for (int i = 0; i < 4; i++)
#pragma unroll
                for (int j = 0; j < 4; j++)
                    s[i][j] = fmaf(a[i], b[j], s[i][j]);
        }

        const bool diag = (kt == qb);
#pragma unroll
        for (int i = 0; i < 4; i++) {
            const int qi = 4 * ty + i;
#pragma unroll
            for (int j = 0; j < 4; j++) {
                const int ki = 4 * tx + j;
                const int bidx = qi - ki + 63;
                float e = 0.f;
#pragma unroll
                for (int n = 0; n < NB; n++)
                    e = fmaf(r_frag[i][n], S.Bsl[n][bidx], e);
                s[i][j] += e;
                if (diag && ki > qi) s[i][j] = -1e30f;
            }
        }

#pragma unroll
        for (int i = 0; i < 4; i++) {
            float mt = fmaxf(fmaxf(s[i][0], s[i][1]), fmaxf(s[i][2], s[i][3]));
#pragma unroll
            for (int o = 8; o > 0; o >>= 1)
                mt = fmaxf(mt, __shfl_xor_sync(0xffffffffu, mt, o));
            float mn = fmaxf(m_run[i], mt);
            float corr = __expf(m_run[i] - mn);
            float ps = 0.f;
#pragma unroll
            for (int j = 0; j < 4; j++) {
                float p = __expf(s[i][j] - mn);
                ps += p;
                S.Ps[4 * tx + j][4 * ty + i] = p;
            }
#pragma unroll
            for (int o = 8; o > 0; o >>= 1)
                ps += __shfl_xor_sync(0xffffffffu, ps, o);
            l_run[i] = l_run[i] * corr + ps;
            m_run[i] = mn;
#pragma unroll
            for (int j = 0; j < 4; j++) o_acc[i][j] *= corr;
        }
        __syncthreads();

#pragma unroll
        for (int k = 0; k < 64; k++) {
            float a[4], b[4];
            float4 af = *reinterpret_cast<float4*>(&S.Ps[k][4 * ty]);
            float4 bf = *reinterpret_cast<float4*>(&S.Vs[k][4 * tx]);
            a[0] = af.x; a[1] = af.y; a[2] = af.z; a[3] = af.w;
            b[0] = bf.x; b[1] = bf.y; b[2] = bf.z; b[3] = bf.w;
#pragma unroll
            for (int i = 0; i < 4; i++)
#pragma unroll
                for (int j = 0; j < 4; j++)
                    o_acc[i][j] = fmaf(a[i], b[j], o_acc[i][j]);
        }
    }

#pragma unroll
    for (int i = 0; i < 4; i++) {
        float inv = 1.f / l_run[i];
        int row = q0 + 4 * ty + i;
#pragma unroll
        for (int j = 0; j < 4; j++)
            AO[(size_t)row * E_DIM + h * D_HEAD + 4 * tx + j] = o_acc[i][j] * inv;
    }
}

// ---------------------------------------------------------------------------
// Host launcher
// ---------------------------------------------------------------------------
extern "C" void kernel_launch(void* const* d_in, const int* in_sizes, int n_in,
                              void* d_out, int out_size)
{
    const float* X      = (const float*)d_in[0];
    const float* W_q    = (const float*)d_in[1];
    const float* b_q    = (const float*)d_in[2];
    const float* W_k    = (const float*)d_in[3];
    const float* W_v    = (const float*)d_in[4];
    const float* W_proj = (const float*)d_in[5];
    const float* b_proj = (const float*)d_in[6];
    const float* W_r    = (const float*)d_in[7];
    const float* b_r    = (const float*)d_in[8];
    const float* b_nd   = (const float*)d_in[9];

    __nv_bfloat16 *Xh, *Xl, *WTh, *WTl, *AOh, *AOl;
    float *QKVRp, *AOp, *biasp;
    cudaGetSymbolAddress((void**)&Xh, g_Xh);
    cudaGetSymbolAddress((void**)&Xl, g_Xl);
    cudaGetSymbolAddress((void**)&WTh, g_WTh);
    cudaGetSymbolAddress((void**)&WTl, g_WTl);
    cudaGetSymbolAddress((void**)&AOh, g_AOh);
    cudaGetSymbolAddress((void**)&AOl, g_AOl);
    cudaGetSymbolAddress((void**)&QKVRp, g_QKVR);
    cudaGetSymbolAddress((void**)&AOp, g_AO);
    cudaGetSymbolAddress((void**)&biasp, g_bias);

    const int nX = T_SEQ * E_DIM;

    // Input splits / weight transposes
    fsplit_kernel<<<(nX + 255) / 256, 256>>>(X, Xh, Xl, nX);
    tsplit_kernel<<<dim3(32, 32), dim3(32, 8)>>>(W_q, 1024, WTh, WTl, 0);
    tsplit_kernel<<<dim3(32, 32), dim3(32, 8)>>>(W_k, 1024, WTh, WTl, 1024);
    tsplit_kernel<<<dim3(32, 32), dim3(32, 8)>>>(W_v, 1024, WTh, WTl, 2048);
    tsplit_kernel<<<dim3(5, 32),  dim3(32, 8)>>>(W_r, 160,  WTh, WTl, 3072);
    tsplit_kernel<<<dim3(32, 32), dim3(32, 8)>>>(W_proj, 1024, WTh, WTl, 3232);
    biaspack_kernel<<<(NQKVR + 255) / 256, 256>>>(b_q, b_r, biasp);

    // Fused QKV+R projection (mma.sync, 3-term bf16 split)
    cudaFuncSetAttribute(gemm_mma3, cudaFuncAttributeMaxDynamicSharedMemorySize, GEMM_SMEM);
    gemm_mma3<<<dim3(26, 16), 256, GEMM_SMEM>>>(Xh, Xl, WTh, WTl, biasp,
                                                QKVRp, NQKVR, NQKVR);

    // Attention (causal flash + relative bias)
    int smem = (int)sizeof(AttnSmem);
    cudaFuncSetAttribute(attn_kernel, cudaFuncAttributeMaxDynamicSharedMemorySize, smem);
    attn_kernel<<<dim3(T_SEQ / 64, N_HEADS), 256, smem>>>(QKVRp, b_nd, AOp);

    // Output projection
    fsplit_kernel<<<(nX + 255) / 256, 256>>>(AOp, AOh, AOl, nX);
    gemm_mma3<<<dim3(8, 16), 256, GEMM_SMEM>>>(AOh, AOl,
                                               WTh + (size_t)3232 * E_DIM,
                                               WTl + (size_t)3232 * E_DIM,
                                               b_proj, (float*)d_out, 1024, 1024);
}

// round 4
// speedup vs baseline: 3.4255x; 2.0388x over previous
#include <cuda_runtime.h>
#include <cuda_bf16.h>
#include <cstdint>

// Problem dims (fixed)
#define T_SEQ 2048
#define E_DIM 1024
#define N_HEADS 16
#define D_HEAD 64
#define NB 10
#define ML 2048
#define NQKVR 3232          // 1024*3 + 160
#define WT_ROWS 4256        // 3232 (QKVR) + 1024 (proj)

// ---------------------------------------------------------------------------
// Scratch (device globals; no runtime allocation allowed)
// ---------------------------------------------------------------------------
__device__ __nv_bfloat16 g_Xh[T_SEQ * E_DIM];
__device__ __nv_bfloat16 g_Xl[T_SEQ * E_DIM];
__device__ __nv_bfloat16 g_WTh[WT_ROWS * E_DIM];
__device__ __nv_bfloat16 g_WTl[WT_ROWS * E_DIM];
__device__ __nv_bfloat16 g_Ph[T_SEQ * 3072];   // QKV hi (Q pre-scaled)
__device__ __nv_bfloat16 g_Pl[T_SEQ * 3072];   // QKV lo
__device__ __nv_bfloat16 g_AOh[T_SEQ * E_DIM];
__device__ __nv_bfloat16 g_AOl[T_SEQ * E_DIM];
__device__ float g_QKVR[T_SEQ * NQKVR];        // only R cols (3072..) used
__device__ float g_bias[NQKVR];

// ---------------------------------------------------------------------------
// PTX helpers (sm_80-baseline ISA only: mma.sync / ldmatrix / cp.async)
// ---------------------------------------------------------------------------
__device__ __forceinline__ uint32_t smem_u32(const void* p) {
    uint32_t a;
    asm("{ .reg .u64 t; cvta.to.shared.u64 t, %1; cvt.u32.u64 %0, t; }"
        : "=r"(a) : "l"(p));
    return a;
}

#define LDSM_X4(r, a)                                                         \
    asm volatile("ldmatrix.sync.aligned.m8n8.x4.shared.b16 {%0,%1,%2,%3}, [%4];" \
                 : "=r"((r)[0]), "=r"((r)[1]), "=r"((r)[2]), "=r"((r)[3])     \
                 : "r"(a))
#define LDSM_X4T(r, a)                                                        \
    asm volatile("ldmatrix.sync.aligned.m8n8.x4.trans.shared.b16 {%0,%1,%2,%3}, [%4];" \
                 : "=r"((r)[0]), "=r"((r)[1]), "=r"((r)[2]), "=r"((r)[3])     \
                 : "r"(a))
#define LDSM_X2(r, a)                                                         \
    asm volatile("ldmatrix.sync.aligned.m8n8.x2.shared.b16 {%0,%1}, [%2];"    \
                 : "=r"((r)[0]), "=r"((r)[1]) : "r"(a))
#define MMA16816(d, a, b)                                                     \
    asm volatile("mma.sync.aligned.m16n8k16.row.col.f32.bf16.bf16.f32 "       \
                 "{%0,%1,%2,%3},{%4,%5,%6,%7},{%8,%9},{%0,%1,%2,%3};"         \
                 : "+f"((d)[0]), "+f"((d)[1]), "+f"((d)[2]), "+f"((d)[3])     \
                 : "r"((a)[0]), "r"((a)[1]), "r"((a)[2]), "r"((a)[3]),        \
                   "r"((b)[0]), "r"((b)[1]))
#define CP_ASYNC16(dst, src)                                                  \
    asm volatile("cp.async.cg.shared.global [%0], [%1], 16;"                  \
                 :: "r"(dst), "l"(src))
#define CP_COMMIT asm volatile("cp.async.commit_group;" ::: "memory")
#define CP_WAIT(n) asm volatile("cp.async.wait_group %0;" :: "n"(n) : "memory")

__device__ __forceinline__ uint32_t pk2(float a, float b) {
    __nv_bfloat162 t = __floats2bfloat162_rn(a, b);   // .x=a (low), .y=b (high)
    return *reinterpret_cast<uint32_t*>(&t);
}

// ---------------------------------------------------------------------------
// Elementwise fp32 -> bf16 hi/lo split (for X)
// ---------------------------------------------------------------------------
__global__ void fsplit_kernel(const float* __restrict__ s,
                              __nv_bfloat16* __restrict__ dh,
                              __nv_bfloat16* __restrict__ dl, int n) {
    int i = blockIdx.x * blockDim.x + threadIdx.x;
    if (i < n) {
        float x = s[i];
        __nv_bfloat16 h = __float2bfloat16(x);
        dh[i] = h;
        dl[i] = __float2bfloat16(x - __bfloat162float(h));
    }
}

// Transpose W [1024][N] -> WT [N][1024] (bf16 hi/lo), rows written at rowoff.
__global__ void tsplit_kernel(const float* __restrict__ W, int N,
                              __nv_bfloat16* __restrict__ dh,
                              __nv_bfloat16* __restrict__ dl, int rowoff) {
    __shared__ float t[32][33];
    const int n0 = blockIdx.x * 32, k0 = blockIdx.y * 32;
    const int tx = threadIdx.x, ty = threadIdx.y;  // 32 x 8
#pragma unroll
    for (int r = 0; r < 4; r++)
        t[ty + 8 * r][tx] = W[(size_t)(k0 + ty + 8 * r) * N + n0 + tx];
    __syncthreads();
#pragma unroll
    for (int r = 0; r < 4; r++) {
        float x = t[tx][ty + 8 * r];
        __nv_bfloat16 h = __float2bfloat16(x);
        size_t o = (size_t)(rowoff + n0 + ty + 8 * r) * E_DIM + k0 + tx;
        dh[o] = h;
        dl[o] = __float2bfloat16(x - __bfloat162float(h));
    }
}

__global__ void biaspack_kernel(const float* __restrict__ bq,
                                const float* __restrict__ br,
                                float* __restrict__ o) {
    int i = blockIdx.x * 256 + threadIdx.x;
    if (i < NQKVR)
        o[i] = i < 1024 ? bq[i] : (i >= 3072 ? br[i - 3072] : 0.f);
}

// ---------------------------------------------------------------------------
// mma.sync GEMM: C[2048, N] = A[2048,1024] @ BT[N,1024]^T (+ bias)
// MODE 0: fp32 output to C (ldc). MODE 1: cols<3072 -> bf16 hi/lo to Oh/Ol
// (Q cols scaled 0.125); cols>=3072 -> fp32 to C (R region).
// ---------------------------------------------------------------------------
#define GEMM_SMEM (2 * 4 * 16384)   // 131072

template <int MODE>
__global__ __launch_bounds__(256, 1) void gemm_mma3(
    const __nv_bfloat16* __restrict__ Ah, const __nv_bfloat16* __restrict__ Al,
    const __nv_bfloat16* __restrict__ Bh, const __nv_bfloat16* __restrict__ Bl,
    const float* __restrict__ bias, float* __restrict__ C,
    __nv_bfloat16* __restrict__ Oh, __nv_bfloat16* __restrict__ Ol,
    int N, int ldc)
{
    extern __shared__ char smraw[];
    const uint32_t sb = smem_u32(smraw);
    const int tid = threadIdx.x, wid = tid >> 5, lane = tid & 31;
    const int m0 = blockIdx.y * 128, n0 = blockIdx.x * 128;
    const int ntile = min(128, N - n0);

    const int wm = (wid & 1) * 64;
    const int wn = (wid >> 1) * 32;

    const __nv_bfloat16* srcs[4];
    srcs[0] = Ah + (size_t)m0 * E_DIM;
    srcs[1] = Al + (size_t)m0 * E_DIM;
    srcs[2] = Bh + (size_t)n0 * E_DIM;
    srcs[3] = Bl + (size_t)n0 * E_DIM;

    auto load_tile = [&](int kt, int buf) {
        const uint32_t base = sb + buf * 65536;
#pragma unroll
        for (int arr = 0; arr < 4; arr++) {
            const __nv_bfloat16* s = srcs[arr] + kt * 64;
#pragma unroll
            for (int i = 0; i < 4; i++) {
                int idx = tid + i * 256;
                int row = idx >> 3, c = idx & 7;
                const void* src = s + (size_t)row * E_DIM + c * 8;
                uint32_t dst = base + arr * 16384 +
                               (uint32_t)(row * 128 + ((c ^ (row & 7)) << 4));
                CP_ASYNC16(dst, src);
            }
        }
    };

    float acc[4][4][4];
#pragma unroll
    for (int mt = 0; mt < 4; mt++)
#pragma unroll
        for (int nt = 0; nt < 4; nt++)
#pragma unroll
            for (int r = 0; r < 4; r++) acc[mt][nt][r] = 0.f;

    const int lr = lane & 7;
    const int ls = lane >> 3;

    load_tile(0, 0);
    CP_COMMIT;

    for (int kt = 0; kt < 16; kt++) {
        if (kt + 1 < 16) {
            load_tile(kt + 1, (kt + 1) & 1);
            CP_COMMIT;
            CP_WAIT(1);
        } else {
            CP_WAIT(0);
        }
        __syncthreads();

        const uint32_t cb = sb + (kt & 1) * 65536;
#pragma unroll
        for (int ks = 0; ks < 4; ks++) {
            uint32_t afh[4][4], afl[4][4], bfh[4][2], bfl[4][2];
#pragma unroll
            for (int mt = 0; mt < 4; mt++) {
                int row = wm + mt * 16 + ((ls & 1) << 3) + lr;
                int ch = (ks << 1) + (ls >> 1);
                uint32_t off = (uint32_t)(row * 128 + ((ch ^ (row & 7)) << 4));
                LDSM_X4(afh[mt], cb + off);
                LDSM_X4(afl[mt], cb + 16384 + off);
            }
#pragma unroll
            for (int nt = 0; nt < 4; nt++) {
                int row = wn + nt * 8 + lr;
                int ch = (ks << 1) + (ls & 1);
                uint32_t off = (uint32_t)(row * 128 + ((ch ^ (row & 7)) << 4));
                LDSM_X2(bfh[nt], cb + 32768 + off);
                LDSM_X2(bfl[nt], cb + 49152 + off);
            }
#pragma unroll
            for (int mt = 0; mt < 4; mt++)
#pragma unroll
                for (int nt = 0; nt < 4; nt++) {
                    MMA16816(acc[mt][nt], afh[mt], bfh[nt]);
                    MMA16816(acc[mt][nt], afh[mt], bfl[nt]);
                    MMA16816(acc[mt][nt], afl[mt], bfh[nt]);
                }
        }
        __syncthreads();
    }

    // ---- epilogue ----
#pragma unroll
    for (int mt = 0; mt < 4; mt++) {
        const int r0 = m0 + wm + mt * 16 + (lane >> 2);
#pragma unroll
        for (int nt = 0; nt < 4; nt++) {
            const int cloc = wn + nt * 8 + ((lane & 3) << 1);
            if (cloc >= ntile) continue;
            const int col = n0 + cloc;
            const float bx = bias[col], by = bias[col + 1];
            float v00 = acc[mt][nt][0] + bx, v01 = acc[mt][nt][1] + by;
            float v10 = acc[mt][nt][2] + bx, v11 = acc[mt][nt][3] + by;
            if (MODE == 0 || col >= 3072) {
                *reinterpret_cast<float2*>(C + (size_t)r0 * ldc + col) =
                    make_float2(v00, v01);
                *reinterpret_cast<float2*>(C + (size_t)(r0 + 8) * ldc + col) =
                    make_float2(v10, v11);
            } else {
                const float sc = (col < 1024) ? 0.125f : 1.f;
                v00 *= sc; v01 *= sc; v10 *= sc; v11 *= sc;
                float h00 = __bfloat162float(__float2bfloat16(v00));
                float h01 = __bfloat162float(__float2bfloat16(v01));
                float h10 = __bfloat162float(__float2bfloat16(v10));
                float h11 = __bfloat162float(__float2bfloat16(v11));
                *reinterpret_cast<uint32_t*>(Oh + (size_t)r0 * 3072 + col) = pk2(h00, h01);
                *reinterpret_cast<uint32_t*>(Ol + (size_t)r0 * 3072 + col) = pk2(v00 - h00, v01 - h01);
                *reinterpret_cast<uint32_t*>(Oh + (size_t)(r0 + 8) * 3072 + col) = pk2(h10, h11);
                *reinterpret_cast<uint32_t*>(Ol + (size_t)(r0 + 8) * 3072 + col) = pk2(v10 - h10, v11 - h11);
            }
        }
    }
}

// ---------------------------------------------------------------------------
// Tensor-core flash-attention with relative banded bias.
// CTA: 128 threads (4 warps), q-tile 64 (warp = 16 rows x full 64 kv cols),
// kv-tile 64. Pairing (qb, 31-qb) -> equal work per CTA. 3-term bf16 splits.
// ---------------------------------------------------------------------------
// smem offsets (bytes)
#define oQH 0u
#define oQL 8192u
#define oKH 16384u
#define oKL 24576u
#define oVH 32768u
#define oVL 40960u
#define oE  49152u            // float[64][132] = 33792 B
#define oBH 82944u            // bf16[128][24]  = 6144 B
#define oBL 89088u
#define oRH 95232u            // bf16[64][24]   = 3072 B
#define oRL 98304u
#define ATTN_SMEM 101376

__device__ __forceinline__ void load_tile64(uint32_t sb, uint32_t off,
                                            const __nv_bfloat16* src, int tid) {
#pragma unroll
    for (int i = 0; i < 4; i++) {
        int idx = tid + i * 128;
        int row = idx >> 3, c = idx & 7;
        uint4 v = *reinterpret_cast<const uint4*>(src + (size_t)row * 3072 + c * 8);
        uint32_t so = sb + off + (uint32_t)(row * 128 + ((c ^ (row & 7)) << 4));
        asm volatile("st.shared.v4.b32 [%0], {%1,%2,%3,%4};"
                     :: "r"(so), "r"(v.x), "r"(v.y), "r"(v.z), "r"(v.w)
                     : "memory");
    }
}

__global__ __launch_bounds__(128) void attn_mma(
    const __nv_bfloat16* __restrict__ Ph, const __nv_bfloat16* __restrict__ Pl,
    const float* __restrict__ QKVR, const float* __restrict__ b_nd,
    __nv_bfloat16* __restrict__ AOh, __nv_bfloat16* __restrict__ AOl)
{
    extern __shared__ char smraw[];
    const uint32_t sb = smem_u32(smraw);
    __nv_bfloat16* Bsh = reinterpret_cast<__nv_bfloat16*>(smraw + oBH);
    __nv_bfloat16* Bsl = reinterpret_cast<__nv_bfloat16*>(smraw + oBL);
    __nv_bfloat16* Rsh = reinterpret_cast<__nv_bfloat16*>(smraw + oRH);
    __nv_bfloat16* Rsl = reinterpret_cast<__nv_bfloat16*>(smraw + oRL);
    float* Ef = reinterpret_cast<float*>(smraw + oE);

    const int tid = threadIdx.x, w = tid >> 5, lane = tid & 31;
    const int h = blockIdx.y;

    const int row_l = (w << 4) + (lane >> 2);   // local q row (0..63)
    const int row_h = row_l + 8;
    const int col_b = (lane & 3) << 1;

    for (int half = 0; half < 2; half++) {
        const int qb = half ? 31 - (int)blockIdx.x : (int)blockIdx.x;
        const int q0 = qb * 64;
        __syncthreads();  // previous half's smem consumers done

        // ---- load Q tile (hi/lo) and R (padded to k=16) ----
        load_tile64(sb, oQH, Ph + (size_t)q0 * 3072 + h * 64, tid);
        load_tile64(sb, oQL, Pl + (size_t)q0 * 3072 + h * 64, tid);
        for (int idx = tid; idx < 64 * 16; idx += 128) {
            int row = idx >> 4, n = idx & 15;
            float v = (n < NB)
                ? QKVR[(size_t)(q0 + row) * NQKVR + 3072 + h * NB + n] : 0.f;
            __nv_bfloat16 hh = __float2bfloat16(v);
            Rsh[row * 24 + n] = hh;
            Rsl[row * 24 + n] = __float2bfloat16(v - __bfloat162float(hh));
        }

        float o[8][4];
#pragma unroll
        for (int nf = 0; nf < 8; nf++)
#pragma unroll
            for (int v = 0; v < 4; v++) o[nf][v] = 0.f;
        float m_run[2] = {-1e30f, -1e30f}, l_run[2] = {0.f, 0.f};

        for (int kt = 0; kt <= qb; kt++) {
            const int k0 = kt * 64;
            __syncthreads();  // previous iteration consumers done (also Q/R ready)

            load_tile64(sb, oKH, Ph + (size_t)k0 * 3072 + 1024 + h * 64, tid);
            load_tile64(sb, oKL, Pl + (size_t)k0 * 3072 + 1024 + h * 64, tid);
            load_tile64(sb, oVH, Ph + (size_t)k0 * 3072 + 2048 + h * 64, tid);
            load_tile64(sb, oVL, Pl + (size_t)k0 * 3072 + 2048 + h * 64, tid);
            {   // BsT slab (transposed, k-padded): row j, cols n
                int j = tid;  // 0..127
                int rel = q0 - k0 - 63 + j;
                bool ok = (rel >= 0) && (rel < ML);
#pragma unroll
                for (int n = 0; n < 16; n++) {
                    float v = (ok && n < NB) ? b_nd[n * ML + rel] : 0.f;
                    __nv_bfloat16 hh = __float2bfloat16(v);
                    Bsh[j * 24 + n] = hh;
                    Bsl[j * 24 + n] = __float2bfloat16(v - __bfloat162float(hh));
                }
            }
            __syncthreads();

            // ---- E = R @ Bslab (64 x 128), per-warp rows ----
            uint32_t aRh[4], aRl[4];
            {
                uint32_t r = (uint32_t)((w << 4) + (lane & 15));
                uint32_t ad = sb + oRH + (r * 24 + ((lane >> 4) << 3)) * 2;
                LDSM_X4(aRh, ad);
                LDSM_X4(aRl, ad + (oRL - oRH));
            }
#pragma unroll
            for (int nf = 0; nf < 16; nf++) {
                float e[4] = {0.f, 0.f, 0.f, 0.f};
                uint32_t bh[2], bl[2];
                uint32_t r = (uint32_t)(nf * 8 + (lane & 7));
                uint32_t ad = sb + oBH + (r * 24 + (((lane >> 3) & 1) << 3)) * 2;
                LDSM_X2(bh, ad);
                LDSM_X2(bl, ad + (oBL - oBH));
                MMA16816(e, aRh, bh);
                MMA16816(e, aRh, bl);
                MMA16816(e, aRl, bh);
                int c = nf * 8 + col_b;
                *reinterpret_cast<float2*>(&Ef[row_l * 132 + c]) = make_float2(e[0], e[1]);
                *reinterpret_cast<float2*>(&Ef[row_h * 132 + c]) = make_float2(e[2], e[3]);
            }
            __syncwarp();

            // ---- S = Q K^T ----
            float s[8][4];
#pragma unroll
            for (int nf = 0; nf < 8; nf++)
#pragma unroll
                for (int v = 0; v < 4; v++) s[nf][v] = 0.f;

#pragma unroll
            for (int ks = 0; ks < 4; ks++) {
                uint32_t aqh[4], aql[4];
                uint32_t qr = (uint32_t)((w << 4) + (lane & 15));
                uint32_t chq = (uint32_t)((ks << 1) + (lane >> 4));
                uint32_t qa = sb + oQH + qr * 128 + ((chq ^ (qr & 7)) << 4);
                LDSM_X4(aqh, qa);
                LDSM_X4(aql, qa + 8192);
#pragma unroll
                for (int nf = 0; nf < 8; nf++) {
                    uint32_t bh[2], bl[2];
                    uint32_t kr = (uint32_t)(nf * 8 + (lane & 7));
                    uint32_t chk = (uint32_t)((ks << 1) + ((lane >> 3) & 1));
                    uint32_t ka = sb + oKH + kr * 128 + ((chk ^ (kr & 7)) << 4);
                    LDSM_X2(bh, ka);
                    LDSM_X2(bl, ka + 8192);
                    MMA16816(s[nf], aqh, bh);
                    MMA16816(s[nf], aqh, bl);
                    MMA16816(s[nf], aql, bh);
                }
            }

            // ---- add gathered bias + causal mask ----
            const bool diag = (kt == qb);
#pragma unroll
            for (int nf = 0; nf < 8; nf++) {
                int c0 = nf * 8 + col_b;
#pragma unroll
                for (int v = 0; v < 4; v++) {
                    int r = (v < 2) ? row_l : row_h;
                    int c = c0 + (v & 1);
                    s[nf][v] += Ef[r * 132 + (r - c + 63)];
                    if (diag && c > r) s[nf][v] = -1e30f;
                }
            }

            // ---- online softmax ----
            float mt0 = -1e30f, mt1 = -1e30f;
#pragma unroll
            for (int nf = 0; nf < 8; nf++) {
                mt0 = fmaxf(mt0, fmaxf(s[nf][0], s[nf][1]));
                mt1 = fmaxf(mt1, fmaxf(s[nf][2], s[nf][3]));
            }
            mt0 = fmaxf(mt0, __shfl_xor_sync(0xffffffffu, mt0, 1));
            mt0 = fmaxf(mt0, __shfl_xor_sync(0xffffffffu, mt0, 2));
            mt1 = fmaxf(mt1, __shfl_xor_sync(0xffffffffu, mt1, 1));
            mt1 = fmaxf(mt1, __shfl_xor_sync(0xffffffffu, mt1, 2));
            float mn0 = fmaxf(m_run[0], mt0), mn1 = fmaxf(m_run[1], mt1);
            float cr0 = __expf(m_run[0] - mn0), cr1 = __expf(m_run[1] - mn1);
            m_run[0] = mn0; m_run[1] = mn1;

            float sum0 = 0.f, sum1 = 0.f;
            uint32_t phk[8][2], plk[8][2];
#pragma unroll
            for (int nf = 0; nf < 8; nf++) {
                float p0 = __expf(s[nf][0] - mn0);
                float p1 = __expf(s[nf][1] - mn0);
                float p2 = __expf(s[nf][2] - mn1);
                float p3 = __expf(s[nf][3] - mn1);
                sum0 += p0 + p1; sum1 += p2 + p3;
                float h0 = __bfloat162float(__float2bfloat16(p0));
                float h1 = __bfloat162float(__float2bfloat16(p1));
                float h2 = __bfloat162float(__float2bfloat16(p2));
                float h3 = __bfloat162float(__float2bfloat16(p3));
                phk[nf][0] = pk2(h0, h1);
                phk[nf][1] = pk2(h2, h3);
                plk[nf][0] = pk2(p0 - h0, p1 - h1);
                plk[nf][1] = pk2(p2 - h2, p3 - h3);
            }
            sum0 += __shfl_xor_sync(0xffffffffu, sum0, 1);
            sum0 += __shfl_xor_sync(0xffffffffu, sum0, 2);
            sum1 += __shfl_xor_sync(0xffffffffu, sum1, 1);
            sum1 += __shfl_xor_sync(0xffffffffu, sum1, 2);
            l_run[0] = l_run[0] * cr0 + sum0;
            l_run[1] = l_run[1] * cr1 + sum1;
#pragma unroll
            for (int nf = 0; nf < 8; nf++) {
                o[nf][0] *= cr0; o[nf][1] *= cr0;
                o[nf][2] *= cr1; o[nf][3] *= cr1;
            }

            // ---- O += P @ V (V via ldmatrix.trans) ----
#pragma unroll
            for (int ks = 0; ks < 4; ks++) {
                uint32_t aH[4] = {phk[2 * ks][0], phk[2 * ks][1],
                                  phk[2 * ks + 1][0], phk[2 * ks + 1][1]};
                uint32_t aL[4] = {plk[2 * ks][0], plk[2 * ks][1],
                                  plk[2 * ks + 1][0], plk[2 * ks + 1][1]};
#pragma unroll
                for (int nfp = 0; nfp < 4; nfp++) {
                    uint32_t bh4[4], bl4[4];
                    uint32_t m = (uint32_t)(lane >> 3);
                    uint32_t vr = (uint32_t)(ks * 16 + ((m & 1) << 3) + (lane & 7));
                    uint32_t chv = (uint32_t)((nfp << 1) + (m >> 1));
                    uint32_t va = sb + oVH + vr * 128 + ((chv ^ (vr & 7)) << 4);
                    LDSM_X4T(bh4, va);
                    LDSM_X4T(bl4, va + 8192);
                    MMA16816(o[2 * nfp], aH, bh4);
                    MMA16816(o[2 * nfp], aL, bh4);
                    MMA16816(o[2 * nfp], aH, bl4);
                    MMA16816(o[2 * nfp + 1], aH, bh4 + 2);
                    MMA16816(o[2 * nfp + 1], aL, bh4 + 2);
                    MMA16816(o[2 * nfp + 1], aH, bl4 + 2);
                }
            }
        } // kv loop

        // ---- epilogue: normalize, split hi/lo, store ----
        float inv0 = 1.f / l_run[0], inv1 = 1.f / l_run[1];
        const size_t rA = (size_t)(q0 + row_l) * E_DIM + h * 64;
        const size_t rB = (size_t)(q0 + row_h) * E_DIM + h * 64;
#pragma unroll
        for (int nf = 0; nf < 8; nf++) {
            int c0 = nf * 8 + col_b;
            float v0 = o[nf][0] * inv0, v1 = o[nf][1] * inv0;
            float v2 = o[nf][2] * inv1, v3 = o[nf][3] * inv1;
            float h0 = __bfloat162float(__float2bfloat16(v0));
            float h1 = __bfloat162float(__float2bfloat16(v1));
            float h2 = __bfloat162float(__float2bfloat16(v2));
            float h3 = __bfloat162float(__float2bfloat16(v3));
            *reinterpret_cast<uint32_t*>(AOh + rA + c0) = pk2(h0, h1);
            *reinterpret_cast<uint32_t*>(AOl + rA + c0) = pk2(v0 - h0, v1 - h1);
            *reinterpret_cast<uint32_t*>(AOh + rB + c0) = pk2(h2, h3);
            *reinterpret_cast<uint32_t*>(AOl + rB + c0) = pk2(v2 - h2, v3 - h3);
        }
    } // half
}

// ---------------------------------------------------------------------------
// Host launcher
// ---------------------------------------------------------------------------
extern "C" void kernel_launch(void* const* d_in, const int* in_sizes, int n_in,
                              void* d_out, int out_size)
{
    const float* X      = (const float*)d_in[0];
    const float* W_q    = (const float*)d_in[1];
    const float* b_q    = (const float*)d_in[2];
    const float* W_k    = (const float*)d_in[3];
    const float* W_v    = (const float*)d_in[4];
    const float* W_proj = (const float*)d_in[5];
    const float* b_proj = (const float*)d_in[6];
    const float* W_r    = (const float*)d_in[7];
    const float* b_r    = (const float*)d_in[8];
    const float* b_nd   = (const float*)d_in[9];

    __nv_bfloat16 *Xh, *Xl, *WTh, *WTl, *Php, *Plp, *AOh, *AOl;
    float *QKVRp, *biasp;
    cudaGetSymbolAddress((void**)&Xh, g_Xh);
    cudaGetSymbolAddress((void**)&Xl, g_Xl);
    cudaGetSymbolAddress((void**)&WTh, g_WTh);
    cudaGetSymbolAddress((void**)&WTl, g_WTl);
    cudaGetSymbolAddress((void**)&Php, g_Ph);
    cudaGetSymbolAddress((void**)&Plp, g_Pl);
    cudaGetSymbolAddress((void**)&AOh, g_AOh);
    cudaGetSymbolAddress((void**)&AOl, g_AOl);
    cudaGetSymbolAddress((void**)&QKVRp, g_QKVR);
    cudaGetSymbolAddress((void**)&biasp, g_bias);

    const int nX = T_SEQ * E_DIM;

    // Input splits / weight transposes
    fsplit_kernel<<<(nX + 255) / 256, 256>>>(X, Xh, Xl, nX);
    tsplit_kernel<<<dim3(32, 32), dim3(32, 8)>>>(W_q, 1024, WTh, WTl, 0);
    tsplit_kernel<<<dim3(32, 32), dim3(32, 8)>>>(W_k, 1024, WTh, WTl, 1024);
    tsplit_kernel<<<dim3(32, 32), dim3(32, 8)>>>(W_v, 1024, WTh, WTl, 2048);
    tsplit_kernel<<<dim3(5, 32),  dim3(32, 8)>>>(W_r, 160,  WTh, WTl, 3072);
    tsplit_kernel<<<dim3(32, 32), dim3(32, 8)>>>(W_proj, 1024, WTh, WTl, 3232);
    biaspack_kernel<<<(NQKVR + 255) / 256, 256>>>(b_q, b_r, biasp);

    // Fused QKV+R projection: QKV -> bf16 hi/lo (Q scaled), R -> fp32
    cudaFuncSetAttribute(gemm_mma3<1>, cudaFuncAttributeMaxDynamicSharedMemorySize, GEMM_SMEM);
    gemm_mma3<1><<<dim3(26, 16), 256, GEMM_SMEM>>>(Xh, Xl, WTh, WTl, biasp,
                                                   QKVRp, Php, Plp, NQKVR, NQKVR);

    // Tensor-core flash attention with relative bias
    cudaFuncSetAttribute(attn_mma, cudaFuncAttributeMaxDynamicSharedMemorySize, ATTN_SMEM);
    attn_mma<<<dim3(16, N_HEADS), 128, ATTN_SMEM>>>(Php, Plp, QKVRp, b_nd, AOh, AOl);

    // Output projection -> d_out (fp32)
    cudaFuncSetAttribute(gemm_mma3<0>, cudaFuncAttributeMaxDynamicSharedMemorySize, GEMM_SMEM);
    gemm_mma3<0><<<dim3(8, 16), 256, GEMM_SMEM>>>(AOh, AOl,
                                                  WTh + (size_t)3232 * E_DIM,
                                                  WTl + (size_t)3232 * E_DIM,
                                                  b_proj, (float*)d_out,
                                                  nullptr, nullptr, 1024, 1024);
}

// round 5
// speedup vs baseline: 3.7453x; 1.0934x over previous
#include <cuda_runtime.h>
#include <cuda_bf16.h>
#include <cstdint>

// Problem dims (fixed)
#define T_SEQ 2048
#define E_DIM 1024
#define N_HEADS 16
#define D_HEAD 64
#define NB 10
#define ML 2048
#define NQKVR 3232          // 1024*3 + 160
#define WT_ROWS 4256        // 3232 (QKVR) + 1024 (proj)

// ---------------------------------------------------------------------------
// Scratch (device globals; no runtime allocation allowed)
// ---------------------------------------------------------------------------
__device__ __nv_bfloat16 g_Xh[T_SEQ * E_DIM];
__device__ __nv_bfloat16 g_Xl[T_SEQ * E_DIM];
__device__ __nv_bfloat16 g_WTh[WT_ROWS * E_DIM];
__device__ __nv_bfloat16 g_WTl[WT_ROWS * E_DIM];
__device__ __nv_bfloat16 g_Ph[T_SEQ * 3072];   // QKV hi (Q pre-scaled)
__device__ __nv_bfloat16 g_Pl[T_SEQ * 3072];   // QKV lo
__device__ __nv_bfloat16 g_AOh[T_SEQ * E_DIM];
__device__ __nv_bfloat16 g_AOl[T_SEQ * E_DIM];
__device__ float g_QKVR[T_SEQ * NQKVR];        // only R cols (3072..) used
__device__ float g_bias[NQKVR];

// ---------------------------------------------------------------------------
// PTX helpers (sm_80-baseline ISA only: mma.sync / ldmatrix / cp.async)
// ---------------------------------------------------------------------------
__device__ __forceinline__ uint32_t smem_u32(const void* p) {
    uint32_t a;
    asm("{ .reg .u64 t; cvta.to.shared.u64 t, %1; cvt.u32.u64 %0, t; }"
        : "=r"(a) : "l"(p));
    return a;
}

#define LDSM_X4(r, a)                                                         \
    asm volatile("ldmatrix.sync.aligned.m8n8.x4.shared.b16 {%0,%1,%2,%3}, [%4];" \
                 : "=r"((r)[0]), "=r"((r)[1]), "=r"((r)[2]), "=r"((r)[3])     \
                 : "r"(a))
#define LDSM_X4T(r, a)                                                        \
    asm volatile("ldmatrix.sync.aligned.m8n8.x4.trans.shared.b16 {%0,%1,%2,%3}, [%4];" \
                 : "=r"((r)[0]), "=r"((r)[1]), "=r"((r)[2]), "=r"((r)[3])     \
                 : "r"(a))
#define LDSM_X2(r, a)                                                         \
    asm volatile("ldmatrix.sync.aligned.m8n8.x2.shared.b16 {%0,%1}, [%2];"    \
                 : "=r"((r)[0]), "=r"((r)[1]) : "r"(a))
#define MMA16816(d, a, b)                                                     \
    asm volatile("mma.sync.aligned.m16n8k16.row.col.f32.bf16.bf16.f32 "       \
                 "{%0,%1,%2,%3},{%4,%5,%6,%7},{%8,%9},{%0,%1,%2,%3};"         \
                 : "+f"((d)[0]), "+f"((d)[1]), "+f"((d)[2]), "+f"((d)[3])     \
                 : "r"((a)[0]), "r"((a)[1]), "r"((a)[2]), "r"((a)[3]),        \
                   "r"((b)[0]), "r"((b)[1]))
#define CP_ASYNC16(dst, src)                                                  \
    asm volatile("cp.async.cg.shared.global [%0], [%1], 16;"                  \
                 :: "r"(dst), "l"(src))
#define CP_COMMIT asm volatile("cp.async.commit_group;" ::: "memory")
#define CP_WAIT(n) asm volatile("cp.async.wait_group %0;" :: "n"(n) : "memory")

__device__ __forceinline__ uint32_t pk2(float a, float b) {
    __nv_bfloat162 t = __floats2bfloat162_rn(a, b);
    return *reinterpret_cast<uint32_t*>(&t);
}
__device__ __forceinline__ float bfr(float x) {
    return __bfloat162float(__float2bfloat16(x));
}

// ---------------------------------------------------------------------------
// Vectorized fp32 -> bf16 hi/lo split (n divisible by 4)
// ---------------------------------------------------------------------------
__global__ void fsplit_kernel(const float* __restrict__ s,
                              __nv_bfloat16* __restrict__ dh,
                              __nv_bfloat16* __restrict__ dl, int n4) {
    int i = blockIdx.x * blockDim.x + threadIdx.x;
    if (i < n4) {
        float4 x = reinterpret_cast<const float4*>(s)[i];
        float h0 = bfr(x.x), h1 = bfr(x.y), h2 = bfr(x.z), h3 = bfr(x.w);
        reinterpret_cast<uint2*>(dh)[i] = make_uint2(pk2(h0, h1), pk2(h2, h3));
        reinterpret_cast<uint2*>(dl)[i] =
            make_uint2(pk2(x.x - h0, x.y - h1), pk2(x.z - h2, x.w - h3));
    }
}

// ---------------------------------------------------------------------------
// Transpose+split: 4 weights [1024][1024] in one launch (z selects weight)
// ---------------------------------------------------------------------------
struct TS4 { const float* w0; const float* w1; const float* w2; const float* w3; };

__global__ void tsplit4_kernel(TS4 p,
                               __nv_bfloat16* __restrict__ dh,
                               __nv_bfloat16* __restrict__ dl) {
    __shared__ float t[32][33];
    const float* W = (&p.w0)[blockIdx.z];
    const int rowoff = (blockIdx.z == 0) ? 0 : (blockIdx.z == 1) ? 1024
                     : (blockIdx.z == 2) ? 2048 : 3232;
    const int n0 = blockIdx.x * 32, k0 = blockIdx.y * 32;
    const int tx = threadIdx.x, ty = threadIdx.y;  // 32 x 8
#pragma unroll
    for (int r = 0; r < 4; r++)
        t[ty + 8 * r][tx] = W[(size_t)(k0 + ty + 8 * r) * 1024 + n0 + tx];
    __syncthreads();
    const int tid = ty * 32 + tx;
#pragma unroll
    for (int rr = 0; rr < 2; rr++) {
        int row = (tid >> 4) + 16 * rr;   // local n
        int c = tid & 15;                 // k pair
        float x0 = t[2 * c][row], x1 = t[2 * c + 1][row];
        float h0 = bfr(x0), h1 = bfr(x1);
        size_t o = (size_t)(rowoff + n0 + row) * E_DIM + k0 + 2 * c;
        *reinterpret_cast<uint32_t*>(dh + o) = pk2(h0, h1);
        *reinterpret_cast<uint32_t*>(dl + o) = pk2(x0 - h0, x1 - h1);
    }
}

// W_r [1024][160] -> rows 3072..3231
__global__ void tsplitR_kernel(const float* __restrict__ W,
                               __nv_bfloat16* __restrict__ dh,
                               __nv_bfloat16* __restrict__ dl) {
    __shared__ float t[32][33];
    const int n0 = blockIdx.x * 32, k0 = blockIdx.y * 32;
    const int tx = threadIdx.x, ty = threadIdx.y;
#pragma unroll
    for (int r = 0; r < 4; r++)
        t[ty + 8 * r][tx] = W[(size_t)(k0 + ty + 8 * r) * 160 + n0 + tx];
    __syncthreads();
    const int tid = ty * 32 + tx;
#pragma unroll
    for (int rr = 0; rr < 2; rr++) {
        int row = (tid >> 4) + 16 * rr;
        int c = tid & 15;
        float x0 = t[2 * c][row], x1 = t[2 * c + 1][row];
        float h0 = bfr(x0), h1 = bfr(x1);
        size_t o = (size_t)(3072 + n0 + row) * E_DIM + k0 + 2 * c;
        *reinterpret_cast<uint32_t*>(dh + o) = pk2(h0, h1);
        *reinterpret_cast<uint32_t*>(dl + o) = pk2(x0 - h0, x1 - h1);
    }
}

__global__ void biaspack_kernel(const float* __restrict__ bq,
                                const float* __restrict__ br,
                                float* __restrict__ o) {
    int i = blockIdx.x * 256 + threadIdx.x;
    if (i < NQKVR)
        o[i] = i < 1024 ? bq[i] : (i >= 3072 ? br[i - 3072] : 0.f);
}

// ---------------------------------------------------------------------------
// mma.sync GEMM: C[2048, N] = A[2048,1024] @ BT[N,1024]^T (+ bias)
// 3-term bf16 split. CTA 128x128, BK=64, 8 warps, 3-stage cp.async pipeline.
// MODE 0: fp32 to C. MODE 1: cols<3072 -> bf16 hi/lo (Q scaled); R -> fp32.
// ---------------------------------------------------------------------------
#define GEMM_SMEM (3 * 4 * 16384)   // 196608

template <int MODE>
__global__ __launch_bounds__(256, 1) void gemm_mma3(
    const __nv_bfloat16* __restrict__ Ah, const __nv_bfloat16* __restrict__ Al,
    const __nv_bfloat16* __restrict__ Bh, const __nv_bfloat16* __restrict__ Bl,
    const float* __restrict__ bias, float* __restrict__ C,
    __nv_bfloat16* __restrict__ Oh, __nv_bfloat16* __restrict__ Ol,
    int N, int ldc)
{
    extern __shared__ char smraw[];
    const uint32_t sb = smem_u32(smraw);
    const int tid = threadIdx.x, wid = tid >> 5, lane = tid & 31;
    const int m0 = blockIdx.y * 128, n0 = blockIdx.x * 128;
    const int ntile = min(128, N - n0);

    const int wm = (wid & 1) * 64;
    const int wn = (wid >> 1) * 32;

    const __nv_bfloat16* srcs[4];
    srcs[0] = Ah + (size_t)m0 * E_DIM;
    srcs[1] = Al + (size_t)m0 * E_DIM;
    srcs[2] = Bh + (size_t)n0 * E_DIM;
    srcs[3] = Bl + (size_t)n0 * E_DIM;

    auto load_tile = [&](int kt, int buf) {
        const uint32_t base = sb + buf * 65536;
#pragma unroll
        for (int arr = 0; arr < 4; arr++) {
            const __nv_bfloat16* s = srcs[arr] + kt * 64;
#pragma unroll
            for (int i = 0; i < 4; i++) {
                int idx = tid + i * 256;
                int row = idx >> 3, c = idx & 7;
                const void* src = s + (size_t)row * E_DIM + c * 8;
                uint32_t dst = base + arr * 16384 +
                               (uint32_t)(row * 128 + ((c ^ (row & 7)) << 4));
                CP_ASYNC16(dst, src);
            }
        }
    };

    float acc[4][4][4];
#pragma unroll
    for (int mt = 0; mt < 4; mt++)
#pragma unroll
        for (int nt = 0; nt < 4; nt++)
#pragma unroll
            for (int r = 0; r < 4; r++) acc[mt][nt][r] = 0.f;

    const int lr = lane & 7;
    const int ls = lane >> 3;

    load_tile(0, 0); CP_COMMIT;
    load_tile(1, 1); CP_COMMIT;

    for (int kt = 0; kt < 16; kt++) {
        if (kt < 14) {
            load_tile(kt + 2, (kt + 2) % 3);
            CP_COMMIT;
            CP_WAIT(2);
        } else if (kt == 14) {
            CP_WAIT(1);
        } else {
            CP_WAIT(0);
        }
        __syncthreads();

        const uint32_t cb = sb + (kt % 3) * 65536;
#pragma unroll
        for (int ks = 0; ks < 4; ks++) {
            uint32_t afh[4][4], afl[4][4], bfh[4][2], bfl[4][2];
#pragma unroll
            for (int mt = 0; mt < 4; mt++) {
                int row = wm + mt * 16 + ((ls & 1) << 3) + lr;
                int ch = (ks << 1) + (ls >> 1);
                uint32_t off = (uint32_t)(row * 128 + ((ch ^ (row & 7)) << 4));
                LDSM_X4(afh[mt], cb + off);
                LDSM_X4(afl[mt], cb + 16384 + off);
            }
#pragma unroll
            for (int nt = 0; nt < 4; nt++) {
                int row = wn + nt * 8 + lr;
                int ch = (ks << 1) + (ls & 1);
                uint32_t off = (uint32_t)(row * 128 + ((ch ^ (row & 7)) << 4));
                LDSM_X2(bfh[nt], cb + 32768 + off);
                LDSM_X2(bfl[nt], cb + 49152 + off);
            }
            // term-major for ILP: 16 independent accumulators per pass
#pragma unroll
            for (int mt = 0; mt < 4; mt++)
#pragma unroll
                for (int nt = 0; nt < 4; nt++)
                    MMA16816(acc[mt][nt], afh[mt], bfh[nt]);
#pragma unroll
            for (int mt = 0; mt < 4; mt++)
#pragma unroll
                for (int nt = 0; nt < 4; nt++)
                    MMA16816(acc[mt][nt], afh[mt], bfl[nt]);
#pragma unroll
            for (int mt = 0; mt < 4; mt++)
#pragma unroll
                for (int nt = 0; nt < 4; nt++)
                    MMA16816(acc[mt][nt], afl[mt], bfh[nt]);
        }
        __syncthreads();
    }

    // ---- epilogue ----
#pragma unroll
    for (int mt = 0; mt < 4; mt++) {
        const int r0 = m0 + wm + mt * 16 + (lane >> 2);
#pragma unroll
        for (int nt = 0; nt < 4; nt++) {
            const int cloc = wn + nt * 8 + ((lane & 3) << 1);
            if (cloc >= ntile) continue;
            const int col = n0 + cloc;
            const float bx = bias[col], by = bias[col + 1];
            float v00 = acc[mt][nt][0] + bx, v01 = acc[mt][nt][1] + by;
            float v10 = acc[mt][nt][2] + bx, v11 = acc[mt][nt][3] + by;
            if (MODE == 0 || col >= 3072) {
                *reinterpret_cast<float2*>(C + (size_t)r0 * ldc + col) =
                    make_float2(v00, v01);
                *reinterpret_cast<float2*>(C + (size_t)(r0 + 8) * ldc + col) =
                    make_float2(v10, v11);
            } else {
                const float sc = (col < 1024) ? 0.125f : 1.f;
                v00 *= sc; v01 *= sc; v10 *= sc; v11 *= sc;
                float h00 = bfr(v00), h01 = bfr(v01);
                float h10 = bfr(v10), h11 = bfr(v11);
                *reinterpret_cast<uint32_t*>(Oh + (size_t)r0 * 3072 + col) = pk2(h00, h01);
                *reinterpret_cast<uint32_t*>(Ol + (size_t)r0 * 3072 + col) = pk2(v00 - h00, v01 - h01);
                *reinterpret_cast<uint32_t*>(Oh + (size_t)(r0 + 8) * 3072 + col) = pk2(h10, h11);
                *reinterpret_cast<uint32_t*>(Ol + (size_t)(r0 + 8) * 3072 + col) = pk2(v10 - h10, v11 - h11);
            }
        }
    }
}

// ---------------------------------------------------------------------------
// Tensor-core flash-attention with relative banded bias.
// 128 threads (4 warps); q-tile 64; kv-tile 64; pairing (qb, 31-qb).
// cp.async K/V overlapped with b_nd split + E-GEMM; term-major MMA order.
// ---------------------------------------------------------------------------
#define oQH 0u
#define oQL 8192u
#define oKH 16384u
#define oKL 24576u
#define oVH 32768u
#define oVL 40960u
#define oE  49152u            // float[64][132] = 33792 B
#define oBH 82944u            // bf16[128][24]  = 6144 B
#define oBL 89088u
#define oRH 95232u            // bf16[64][24]   = 3072 B
#define oRL 98304u
#define ATTN_SMEM 101376

__device__ __forceinline__ void cp_tile64(uint32_t sb, uint32_t off,
                                          const __nv_bfloat16* src, int tid) {
#pragma unroll
    for (int i = 0; i < 4; i++) {
        int idx = tid + i * 128;
        int row = idx >> 3, c = idx & 7;
        uint32_t dst = sb + off + (uint32_t)(row * 128 + ((c ^ (row & 7)) << 4));
        CP_ASYNC16(dst, src + (size_t)row * 3072 + c * 8);
    }
}

__global__ __launch_bounds__(128) void attn_mma(
    const __nv_bfloat16* __restrict__ Ph, const __nv_bfloat16* __restrict__ Pl,
    const float* __restrict__ QKVR, const float* __restrict__ b_nd,
    __nv_bfloat16* __restrict__ AOh, __nv_bfloat16* __restrict__ AOl)
{
    extern __shared__ char smraw[];
    const uint32_t sb = smem_u32(smraw);
    __nv_bfloat16* Bsh = reinterpret_cast<__nv_bfloat16*>(smraw + oBH);
    __nv_bfloat16* Bsl = reinterpret_cast<__nv_bfloat16*>(smraw + oBL);
    __nv_bfloat16* Rsh = reinterpret_cast<__nv_bfloat16*>(smraw + oRH);
    __nv_bfloat16* Rsl = reinterpret_cast<__nv_bfloat16*>(smraw + oRL);
    float* Ef = reinterpret_cast<float*>(smraw + oE);

    const int tid = threadIdx.x, w = tid >> 5, lane = tid & 31;
    const int h = blockIdx.y;

    const int row_l = (w << 4) + (lane >> 2);
    const int row_h = row_l + 8;
    const int col_b = (lane & 3) << 1;

    for (int half = 0; half < 2; half++) {
        const int qb = half ? 31 - (int)blockIdx.x : (int)blockIdx.x;
        const int q0 = qb * 64;
        __syncthreads();  // previous half's smem consumers done

        // ---- async Q tile (hi/lo); R fragment (padded to k=16) ----
        cp_tile64(sb, oQH, Ph + (size_t)q0 * 3072 + h * 64, tid);
        cp_tile64(sb, oQL, Pl + (size_t)q0 * 3072 + h * 64, tid);
        CP_COMMIT;
        for (int idx = tid; idx < 64 * 16; idx += 128) {
            int row = idx >> 4, n = idx & 15;
            float v = (n < NB)
                ? QKVR[(size_t)(q0 + row) * NQKVR + 3072 + h * NB + n] : 0.f;
            float hh = bfr(v);
            Rsh[row * 24 + n] = __float2bfloat16(hh);
            Rsl[row * 24 + n] = __float2bfloat16(v - hh);
        }

        float o[8][4];
#pragma unroll
        for (int nf = 0; nf < 8; nf++)
#pragma unroll
            for (int v = 0; v < 4; v++) o[nf][v] = 0.f;
        float m_run[2] = {-1e30f, -1e30f}, l_run[2] = {0.f, 0.f};

        for (int kt = 0; kt <= qb; kt++) {
            const int k0 = kt * 64;
            __syncthreads();  // prev iter compute done (V/B/E consumers)

            // prefetch b_nd values (global latency overlapped below)
            float bv[NB];
            {
                int rel = q0 - k0 - 63 + tid;
                bool ok = (rel >= 0) && (rel < ML);
#pragma unroll
                for (int n = 0; n < NB; n++)
                    bv[n] = ok ? __ldg(b_nd + n * ML + rel) : 0.f;
            }

            // async K/V tiles (hi/lo)
            cp_tile64(sb, oKH, Ph + (size_t)k0 * 3072 + 1024 + h * 64, tid);
            cp_tile64(sb, oKL, Pl + (size_t)k0 * 3072 + 1024 + h * 64, tid);
            cp_tile64(sb, oVH, Ph + (size_t)k0 * 3072 + 2048 + h * 64, tid);
            cp_tile64(sb, oVL, Pl + (size_t)k0 * 3072 + 2048 + h * 64, tid);
            CP_COMMIT;

            // B slab split (row tid)
#pragma unroll
            for (int n = 0; n < 16; n++) {
                float v = (n < NB) ? bv[n] : 0.f;
                float hh = bfr(v);
                Bsh[tid * 24 + n] = __float2bfloat16(hh);
                Bsl[tid * 24 + n] = __float2bfloat16(v - hh);
            }
            __syncthreads();  // B (and R/Q smem writes) visible

            // ---- E = R @ Bslab (64 x 128) ----
            uint32_t aRh[4], aRl[4];
            {
                uint32_t r = (uint32_t)((w << 4) + (lane & 15));
                uint32_t ad = sb + oRH + (r * 24 + ((lane >> 4) << 3)) * 2;
                LDSM_X4(aRh, ad);
                LDSM_X4(aRl, ad + (oRL - oRH));
            }
#pragma unroll
            for (int g = 0; g < 4; g++) {
                uint32_t bh[4][2], bl[4][2];
                float e[4][4];
#pragma unroll
                for (int j = 0; j < 4; j++) {
                    uint32_t r = (uint32_t)((4 * g + j) * 8 + (lane & 7));
                    uint32_t ad = sb + oBH + (r * 24 + (((lane >> 3) & 1) << 3)) * 2;
                    LDSM_X2(bh[j], ad);
                    LDSM_X2(bl[j], ad + (oBL - oBH));
#pragma unroll
                    for (int v = 0; v < 4; v++) e[j][v] = 0.f;
                }
#pragma unroll
                for (int j = 0; j < 4; j++) MMA16816(e[j], aRh, bh[j]);
#pragma unroll
                for (int j = 0; j < 4; j++) MMA16816(e[j], aRh, bl[j]);
#pragma unroll
                for (int j = 0; j < 4; j++) MMA16816(e[j], aRl, bh[j]);
#pragma unroll
                for (int j = 0; j < 4; j++) {
                    int c = (4 * g + j) * 8 + col_b;
                    *reinterpret_cast<float2*>(&Ef[row_l * 132 + c]) =
                        make_float2(e[j][0], e[j][1]);
                    *reinterpret_cast<float2*>(&Ef[row_h * 132 + c]) =
                        make_float2(e[j][2], e[j][3]);
                }
            }
            __syncwarp();

            CP_WAIT(0);
            __syncthreads();  // K/V landed; Ef visible

            // ---- S = Q K^T (term-major) ----
            float s[8][4];
#pragma unroll
            for (int nf = 0; nf < 8; nf++)
#pragma unroll
                for (int v = 0; v < 4; v++) s[nf][v] = 0.f;

#pragma unroll
            for (int ks = 0; ks < 4; ks++) {
                uint32_t aqh[4], aql[4];
                uint32_t qr = (uint32_t)((w << 4) + (lane & 15));
                uint32_t chq = (uint32_t)((ks << 1) + (lane >> 4));
                uint32_t qa = sb + oQH + qr * 128 + ((chq ^ (qr & 7)) << 4);
                LDSM_X4(aqh, qa);
                LDSM_X4(aql, qa + 8192);
                uint32_t bh[8][2], bl[8][2];
#pragma unroll
                for (int nf = 0; nf < 8; nf++) {
                    uint32_t kr = (uint32_t)(nf * 8 + (lane & 7));
                    uint32_t chk = (uint32_t)((ks << 1) + ((lane >> 3) & 1));
                    uint32_t ka = sb + oKH + kr * 128 + ((chk ^ (kr & 7)) << 4);
                    LDSM_X2(bh[nf], ka);
                    LDSM_X2(bl[nf], ka + 8192);
                }
#pragma unroll
                for (int nf = 0; nf < 8; nf++) MMA16816(s[nf], aqh, bh[nf]);
#pragma unroll
                for (int nf = 0; nf < 8; nf++) MMA16816(s[nf], aqh, bl[nf]);
#pragma unroll
                for (int nf = 0; nf < 8; nf++) MMA16816(s[nf], aql, bh[nf]);
            }

            // ---- gathered bias + causal mask ----
            const bool diag = (kt == qb);
#pragma unroll
            for (int nf = 0; nf < 8; nf++) {
                int c0 = nf * 8 + col_b;
#pragma unroll
                for (int v = 0; v < 4; v++) {
                    int r = (v < 2) ? row_l : row_h;
                    int c = c0 + (v & 1);
                    s[nf][v] += Ef[r * 132 + (r - c + 63)];
                    if (diag && c > r) s[nf][v] = -1e30f;
                }
            }

            // ---- online softmax ----
            float mt0 = -1e30f, mt1 = -1e30f;
#pragma unroll
            for (int nf = 0; nf < 8; nf++) {
                mt0 = fmaxf(mt0, fmaxf(s[nf][0], s[nf][1]));
                mt1 = fmaxf(mt1, fmaxf(s[nf][2], s[nf][3]));
            }
            mt0 = fmaxf(mt0, __shfl_xor_sync(0xffffffffu, mt0, 1));
            mt0 = fmaxf(mt0, __shfl_xor_sync(0xffffffffu, mt0, 2));
            mt1 = fmaxf(mt1, __shfl_xor_sync(0xffffffffu, mt1, 1));
            mt1 = fmaxf(mt1, __shfl_xor_sync(0xffffffffu, mt1, 2));
            float mn0 = fmaxf(m_run[0], mt0), mn1 = fmaxf(m_run[1], mt1);
            float cr0 = __expf(m_run[0] - mn0), cr1 = __expf(m_run[1] - mn1);
            m_run[0] = mn0; m_run[1] = mn1;

            float sum0 = 0.f, sum1 = 0.f;
            uint32_t phk[8][2], plk[8][2];
#pragma unroll
            for (int nf = 0; nf < 8; nf++) {
                float p0 = __expf(s[nf][0] - mn0);
                float p1 = __expf(s[nf][1] - mn0);
                float p2 = __expf(s[nf][2] - mn1);
                float p3 = __expf(s[nf][3] - mn1);
                sum0 += p0 + p1; sum1 += p2 + p3;
                float h0 = bfr(p0), h1 = bfr(p1), h2 = bfr(p2), h3 = bfr(p3);
                phk[nf][0] = pk2(h0, h1);
                phk[nf][1] = pk2(h2, h3);
                plk[nf][0] = pk2(p0 - h0, p1 - h1);
                plk[nf][1] = pk2(p2 - h2, p3 - h3);
            }
            sum0 += __shfl_xor_sync(0xffffffffu, sum0, 1);
            sum0 += __shfl_xor_sync(0xffffffffu, sum0, 2);
            sum1 += __shfl_xor_sync(0xffffffffu, sum1, 1);
            sum1 += __shfl_xor_sync(0xffffffffu, sum1, 2);
            l_run[0] = l_run[0] * cr0 + sum0;
            l_run[1] = l_run[1] * cr1 + sum1;
#pragma unroll
            for (int nf = 0; nf < 8; nf++) {
                o[nf][0] *= cr0; o[nf][1] *= cr0;
                o[nf][2] *= cr1; o[nf][3] *= cr1;
            }

            // ---- O += P @ V (term-major) ----
#pragma unroll
            for (int ks = 0; ks < 4; ks++) {
                uint32_t aH[4] = {phk[2 * ks][0], phk[2 * ks][1],
                                  phk[2 * ks + 1][0], phk[2 * ks + 1][1]};
                uint32_t aL[4] = {plk[2 * ks][0], plk[2 * ks][1],
                                  plk[2 * ks + 1][0], plk[2 * ks + 1][1]};
                uint32_t vh[4][4], vl[4][4];
#pragma unroll
                for (int nfp = 0; nfp < 4; nfp++) {
                    uint32_t m = (uint32_t)(lane >> 3);
                    uint32_t vr = (uint32_t)(ks * 16 + ((m & 1) << 3) + (lane & 7));
                    uint32_t chv = (uint32_t)((nfp << 1) + (m >> 1));
                    uint32_t va = sb + oVH + vr * 128 + ((chv ^ (vr & 7)) << 4);
                    LDSM_X4T(vh[nfp], va);
                    LDSM_X4T(vl[nfp], va + 8192);
                }
#pragma unroll
                for (int nfp = 0; nfp < 4; nfp++) {
                    MMA16816(o[2 * nfp], aH, vh[nfp]);
                    MMA16816(o[2 * nfp + 1], aH, vh[nfp] + 2);
                }
#pragma unroll
                for (int nfp = 0; nfp < 4; nfp++) {
                    MMA16816(o[2 * nfp], aL, vh[nfp]);
                    MMA16816(o[2 * nfp + 1], aL, vh[nfp] + 2);
                }
#pragma unroll
                for (int nfp = 0; nfp < 4; nfp++) {
                    MMA16816(o[2 * nfp], aH, vl[nfp]);
                    MMA16816(o[2 * nfp + 1], aH, vl[nfp] + 2);
                }
            }
        } // kv loop

        // ---- epilogue: normalize, split hi/lo, store ----
        float inv0 = 1.f / l_run[0], inv1 = 1.f / l_run[1];
        const size_t rA = (size_t)(q0 + row_l) * E_DIM + h * 64;
        const size_t rB = (size_t)(q0 + row_h) * E_DIM + h * 64;
#pragma unroll
        for (int nf = 0; nf < 8; nf++) {
            int c0 = nf * 8 + col_b;
            float v0 = o[nf][0] * inv0, v1 = o[nf][1] * inv0;
            float v2 = o[nf][2] * inv1, v3 = o[nf][3] * inv1;
            float h0 = bfr(v0), h1 = bfr(v1), h2 = bfr(v2), h3 = bfr(v3);
            *reinterpret_cast<uint32_t*>(AOh + rA + c0) = pk2(h0, h1);
            *reinterpret_cast<uint32_t*>(AOl + rA + c0) = pk2(v0 - h0, v1 - h1);
            *reinterpret_cast<uint32_t*>(AOh + rB + c0) = pk2(h2, h3);
            *reinterpret_cast<uint32_t*>(AOl + rB + c0) = pk2(v2 - h2, v3 - h3);
        }
    } // half
}

// ---------------------------------------------------------------------------
// Host launcher
// ---------------------------------------------------------------------------
extern "C" void kernel_launch(void* const* d_in, const int* in_sizes, int n_in,
                              void* d_out, int out_size)
{
    const float* X      = (const float*)d_in[0];
    const float* W_q    = (const float*)d_in[1];
    const float* b_q    = (const float*)d_in[2];
    const float* W_k    = (const float*)d_in[3];
    const float* W_v    = (const float*)d_in[4];
    const float* W_proj = (const float*)d_in[5];
    const float* b_proj = (const float*)d_in[6];
    const float* W_r    = (const float*)d_in[7];
    const float* b_r    = (const float*)d_in[8];
    const float* b_nd   = (const float*)d_in[9];

    __nv_bfloat16 *Xh, *Xl, *WTh, *WTl, *Php, *Plp, *AOh, *AOl;
    float *QKVRp, *biasp;
    cudaGetSymbolAddress((void**)&Xh, g_Xh);
    cudaGetSymbolAddress((void**)&Xl, g_Xl);
    cudaGetSymbolAddress((void**)&WTh, g_WTh);
    cudaGetSymbolAddress((void**)&WTl, g_WTl);
    cudaGetSymbolAddress((void**)&Php, g_Ph);
    cudaGetSymbolAddress((void**)&Plp, g_Pl);
    cudaGetSymbolAddress((void**)&AOh, g_AOh);
    cudaGetSymbolAddress((void**)&AOl, g_AOl);
    cudaGetSymbolAddress((void**)&QKVRp, g_QKVR);
    cudaGetSymbolAddress((void**)&biasp, g_bias);

    const int nX = T_SEQ * E_DIM;

    // (0) X split
    fsplit_kernel<<<(nX / 4 + 255) / 256, 256>>>(X, Xh, Xl, nX / 4);
    // (1) four 1024-wide weights in one launch
    TS4 ts4 = {W_q, W_k, W_v, W_proj};
    tsplit4_kernel<<<dim3(32, 32, 4), dim3(32, 8)>>>(ts4, WTh, WTl);
    // (2) W_r
    tsplitR_kernel<<<dim3(5, 32), dim3(32, 8)>>>(W_r, WTh, WTl);
    // (3) bias pack
    biaspack_kernel<<<(NQKVR + 255) / 256, 256>>>(b_q, b_r, biasp);

    // (4) fused QKV+R projection
    cudaFuncSetAttribute(gemm_mma3<1>, cudaFuncAttributeMaxDynamicSharedMemorySize, GEMM_SMEM);
    gemm_mma3<1><<<dim3(26, 16), 256, GEMM_SMEM>>>(Xh, Xl, WTh, WTl, biasp,
                                                   QKVRp, Php, Plp, NQKVR, NQKVR);

    // (5) tensor-core flash attention  <-- ncu -s 5 profiles this
    cudaFuncSetAttribute(attn_mma, cudaFuncAttributeMaxDynamicSharedMemorySize, ATTN_SMEM);
    attn_mma<<<dim3(16, N_HEADS), 128, ATTN_SMEM>>>(Php, Plp, QKVRp, b_nd, AOh, AOl);

    // (6) output projection -> d_out (fp32)
    cudaFuncSetAttribute(gemm_mma3<0>, cudaFuncAttributeMaxDynamicSharedMemorySize, GEMM_SMEM);
    gemm_mma3<0><<<dim3(8, 16), 256, GEMM_SMEM>>>(AOh, AOl,
                                                  WTh + (size_t)3232 * E_DIM,
                                                  WTl + (size_t)3232 * E_DIM,
                                                  b_proj, (float*)d_out,
                                                  nullptr, nullptr, 1024, 1024);
}